// round 2
// baseline (speedup 1.0000x reference)
#include <cuda_runtime.h>
#include <math.h>

// ---------------- problem constants (fixed shapes) ----------------
#define L_    4
#define B_    8
#define SQ    512
#define D_    1024
#define H_    16
#define DHD   64
#define T_    (B_*SQ)       // 4096
#define FFN_  4096
#define PAGE_ 16
#define PPS   80            // pages per seq
#define CACHED 48
#define KV    1280          // kv length per seq
#define NUM_PAGES 640

// ---------------- device scratch (no allocations allowed) ----------------
__device__ float g_x[T_*D_];         // current activations
__device__ float g_q[T_*D_];
__device__ float g_k[T_*D_];
__device__ float g_v[T_*D_];
__device__ float g_attn[T_*D_];      // attention output (pre-Wo)
__device__ float g_tmp[T_*D_];       // projection output
__device__ float g_h[T_*FFN_];       // FFN hidden
__device__ float g_Kf[B_*KV*D_];     // gathered K  [B][KV][H*DH]
__device__ float g_Vf[B_*KV*D_];     // gathered V
__device__ float g_S[(size_t)B_*H_*SQ*KV];  // attention scores/probs

// ---------------- generic tiled fp32 GEMM (double-buffered smem) ----------------
// C[m][n] = alpha * sum_k A[m][k] * B(op)[k][n]  (+ bias[n]) (+ GELU)
// TB=false: B accessed as B[k*ldb + n]  (NN)
// TB=true : B accessed as B[n*ldb + k]  (NT)
// Batched via blockIdx.z: z -> (zb = z/Hn, zh = z%Hn), pointer offsets.
// Tile: 128x128x8, 256 threads, 8x8 micro-tile per thread.
// Requirements: M % 128 == 0, K % 16 == 0, lda/ldb/ldc % 4 == 0, N % 4 == 0
// (N may be < 128: B-NN loads and C stores predicated on n < N).
template<bool TB, bool GELU>
__global__ void __launch_bounds__(256)
gemm_k(const float* __restrict__ A, const float* __restrict__ Bm,
       const float* __restrict__ bias, float* __restrict__ C,
       int M, int N, int K, int lda, int ldb, int ldc,
       int Hn, long aS, long aH, long bS, long bH, long cS, long cH,
       float alpha)
{
    const int z  = blockIdx.z;
    const int zb = z / Hn;
    const int zh = z - zb * Hn;
    A  += zb*aS + zh*aH;
    Bm += zb*bS + zh*bH;
    C  += zb*cS + zh*cH;

    __shared__ float As[2][8][128];
    __shared__ float Bs[2][8][128];

    const int bm  = blockIdx.y * 128;
    const int bn  = blockIdx.x * 128;
    const int tid = threadIdx.x;
    const int tx  = tid & 15;    // 0..15
    const int ty  = tid >> 4;    // 0..15

    float acc[8][8];
    #pragma unroll
    for (int i = 0; i < 8; i++)
        #pragma unroll
        for (int j = 0; j < 8; j++) acc[i][j] = 0.f;

    // A tile loader: 128 rows x 8 k, one float4 per thread along K
    const int arow = tid >> 1;            // 0..127
    const int akc  = (tid & 1) * 4;       // 0 or 4
    // B NN loader: 8 k-rows x 128 n, one float4 per thread along N
    const int bkr  = tid >> 5;            // 0..7
    const int bnc  = (tid & 31) * 4;      // 0..124
    const bool bok = (bn + bnc) < N;      // n-predicate (k-independent)
    // B NT loader: 128 n-rows x 8 k, one float4 per thread along K
    const int bnr  = tid >> 1;            // 0..127
    const int bkc  = (tid & 1) * 4;       // 0 or 4

    const float* Ald = &A[(long)(bm + arow) * lda + akc];
    const float* Bld = TB ? &Bm[(long)(bn + bnr) * ldb + bkc]
                          : &Bm[(long)bkr * ldb + bn + bnc];

    // ---- prologue: load k-tile 0 into buffer 0 ----
    {
        const float4 av = *reinterpret_cast<const float4*>(Ald);
        As[0][akc+0][arow] = av.x; As[0][akc+1][arow] = av.y;
        As[0][akc+2][arow] = av.z; As[0][akc+3][arow] = av.w;
        if (TB) {
            const float4 bv = *reinterpret_cast<const float4*>(Bld);
            Bs[0][bkc+0][bnr] = bv.x; Bs[0][bkc+1][bnr] = bv.y;
            Bs[0][bkc+2][bnr] = bv.z; Bs[0][bkc+3][bnr] = bv.w;
        } else {
            float4 bv = make_float4(0.f, 0.f, 0.f, 0.f);
            if (bok) bv = *reinterpret_cast<const float4*>(Bld);
            *reinterpret_cast<float4*>(&Bs[0][bkr][bnc]) = bv;
        }
    }
    __syncthreads();

    const int nk = K >> 3;
    for (int kt = 0; kt < nk; kt++) {
        const int buf = kt & 1;
        const bool more = (kt + 1) < nk;

        // ---- prefetch next k-tile into registers ----
        float4 av_n, bv_n;
        if (more) {
            const long ko = (long)(kt + 1) * 8;
            av_n = *reinterpret_cast<const float4*>(Ald + ko);
            if (TB) {
                bv_n = *reinterpret_cast<const float4*>(Bld + ko);
            } else {
                bv_n = make_float4(0.f, 0.f, 0.f, 0.f);
                if (bok) bv_n = *reinterpret_cast<const float4*>(Bld + ko * ldb);
            }
        }

        // ---- compute on current buffer ----
        #pragma unroll
        for (int kk = 0; kk < 8; kk++) {
            float a[8], b[8];
            *reinterpret_cast<float4*>(a)     = *reinterpret_cast<const float4*>(&As[buf][kk][ty*4]);
            *reinterpret_cast<float4*>(a + 4) = *reinterpret_cast<const float4*>(&As[buf][kk][64 + ty*4]);
            *reinterpret_cast<float4*>(b)     = *reinterpret_cast<const float4*>(&Bs[buf][kk][tx*4]);
            *reinterpret_cast<float4*>(b + 4) = *reinterpret_cast<const float4*>(&Bs[buf][kk][64 + tx*4]);
            #pragma unroll
            for (int i = 0; i < 8; i++)
                #pragma unroll
                for (int j = 0; j < 8; j++)
                    acc[i][j] = fmaf(a[i], b[j], acc[i][j]);
        }

        // ---- write prefetched tile into the other buffer ----
        if (more) {
            const int nb = buf ^ 1;
            As[nb][akc+0][arow] = av_n.x; As[nb][akc+1][arow] = av_n.y;
            As[nb][akc+2][arow] = av_n.z; As[nb][akc+3][arow] = av_n.w;
            if (TB) {
                Bs[nb][bkc+0][bnr] = bv_n.x; Bs[nb][bkc+1][bnr] = bv_n.y;
                Bs[nb][bkc+2][bnr] = bv_n.z; Bs[nb][bkc+3][bnr] = bv_n.w;
            } else {
                *reinterpret_cast<float4*>(&Bs[nb][bkr][bnc]) = bv_n;
            }
        }
        __syncthreads();
    }

    // ---- epilogue + store (float4, predicated on n < N) ----
    #pragma unroll
    for (int i = 0; i < 8; i++) {
        const int m = bm + ((i < 4) ? (ty*4 + i) : (64 + ty*4 + (i - 4)));
        #pragma unroll
        for (int jg = 0; jg < 2; jg++) {
            const int n0 = bn + ((jg == 0) ? tx*4 : 64 + tx*4);
            if (n0 < N) {
                float vx[4];
                #pragma unroll
                for (int j = 0; j < 4; j++) {
                    float val = acc[i][jg*4 + j] * alpha;
                    if (bias) val += bias[n0 + j];
                    if (GELU) val = 0.5f * val * (1.f + erff(val * 0.70710678118654752f));
                    vx[j] = val;
                }
                *reinterpret_cast<float4*>(&C[(long)m * ldc + n0]) =
                    make_float4(vx[0], vx[1], vx[2], vx[3]);
            }
        }
    }
}

// ---------------- gather paged KV into dense [B][KV][H*DH] ----------------
// Cached pages (slot < 48) come from the (read-only) input pagetable for this
// layer; new-token pages come directly from g_k / g_v (identical to the
// reference's write-then-gather, without mutating the input).
__global__ void gather_kv_k(const float* __restrict__ PT,   // pagetable + l offset
                            const int*   __restrict__ idx,  // paged_kv_indices
                            const float* __restrict__ kk,
                            const float* __restrict__ vv)
{
    const long e = (long)blockIdx.x * 256 + threadIdx.x;   // over B*KV*D_
    const int b     = (int)(e / (KV * D_));
    const int r     = (int)(e % (KV * D_));
    const int kvpos = r / D_;
    const int c     = r % D_;               // h*64 + dh
    const int slot  = kvpos >> 4;
    const int off   = kvpos & 15;
    if (slot < CACHED) {
        const int  pid  = idx[b * PPS + slot];
        const long base = (long)pid * (2 * PAGE_ * H_ * DHD) + (long)off * (H_ * DHD) + c;
        g_Kf[e] = PT[base];
        g_Vf[e] = PT[base + PAGE_ * H_ * DHD];
    } else {
        const int t = b * SQ + (slot - CACHED) * PAGE_ + off;
        g_Kf[e] = kk[(long)t * D_ + c];
        g_Vf[e] = vv[(long)t * D_ + c];
    }
}

// ---------------- rowwise softmax over KV=1280 (in place) ----------------
__global__ void softmax_k(float* __restrict__ S)
{
    float* row = S + (long)blockIdx.x * KV;
    const int tid = threadIdx.x;   // 128 threads, 10 elems each
    float v[10];
    float mx = -1e30f;
    #pragma unroll
    for (int i = 0; i < 10; i++) { v[i] = row[tid + i*128]; mx = fmaxf(mx, v[i]); }

    __shared__ float redm[4], reds[4];
    #pragma unroll
    for (int o = 16; o; o >>= 1) mx = fmaxf(mx, __shfl_xor_sync(0xffffffffu, mx, o));
    if ((tid & 31) == 0) redm[tid >> 5] = mx;
    __syncthreads();
    mx = fmaxf(fmaxf(redm[0], redm[1]), fmaxf(redm[2], redm[3]));

    float s = 0.f;
    #pragma unroll
    for (int i = 0; i < 10; i++) { v[i] = expf(v[i] - mx); s += v[i]; }
    #pragma unroll
    for (int o = 16; o; o >>= 1) s += __shfl_xor_sync(0xffffffffu, s, o);
    if ((tid & 31) == 0) reds[tid >> 5] = s;
    __syncthreads();
    s = reds[0] + reds[1] + reds[2] + reds[3];
    const float inv = 1.f / s;
    #pragma unroll
    for (int i = 0; i < 10; i++) row[tid + i*128] = v[i] * inv;
}

// ---------------- fused residual-add + layernorm (in place on x) ----------------
__global__ void add_ln_k(float* __restrict__ x, const float* __restrict__ y,
                         const float* __restrict__ g, const float* __restrict__ b)
{
    const int row = blockIdx.x;
    const int tid = threadIdx.x;   // 256 threads, 4 elems each
    float v[4];
    float s = 0.f, s2 = 0.f;
    #pragma unroll
    for (int i = 0; i < 4; i++) {
        const int c = tid + i*256;
        const float t = x[(long)row*D_ + c] + y[(long)row*D_ + c];
        v[i] = t; s += t; s2 += t*t;
    }
    __shared__ float rs[8], rs2[8];
    #pragma unroll
    for (int o = 16; o; o >>= 1) {
        s  += __shfl_xor_sync(0xffffffffu, s,  o);
        s2 += __shfl_xor_sync(0xffffffffu, s2, o);
    }
    if ((tid & 31) == 0) { rs[tid >> 5] = s; rs2[tid >> 5] = s2; }
    __syncthreads();
    s = 0.f; s2 = 0.f;
    #pragma unroll
    for (int w = 0; w < 8; w++) { s += rs[w]; s2 += rs2[w]; }
    const float mean = s * (1.f / D_);
    const float var  = s2 * (1.f / D_) - mean * mean;
    const float rstd = rsqrtf(var + 1e-5f);
    #pragma unroll
    for (int i = 0; i < 4; i++) {
        const int c = tid + i*256;
        x[(long)row*D_ + c] = (v[i] - mean) * rstd * g[c] + b[c];
    }
}

__global__ void copy_k(float* __restrict__ dst, const float* __restrict__ src, int n)
{
    const int i = blockIdx.x * 256 + threadIdx.x;
    if (i < n) dst[i] = src[i];
}

// ---------------- launch ----------------
extern "C" void kernel_launch(void* const* d_in, const int* in_sizes, int n_in,
                              void* d_out, int out_size)
{
    const float* x         = (const float*)d_in[0];
    const int*   kvidx     = (const int*)  d_in[3];
    const float* pagetable = (const float*)d_in[5];
    const float* Wq  = (const float*)d_in[6];
    const float* bq  = (const float*)d_in[7];
    const float* Wk  = (const float*)d_in[8];
    const float* bk  = (const float*)d_in[9];
    const float* Wv  = (const float*)d_in[10];
    const float* bv  = (const float*)d_in[11];
    const float* Wo  = (const float*)d_in[12];
    const float* bo  = (const float*)d_in[13];
    const float* l1g = (const float*)d_in[14];
    const float* l1b = (const float*)d_in[15];
    const float* W1  = (const float*)d_in[16];
    const float* b1  = (const float*)d_in[17];
    const float* W2  = (const float*)d_in[18];
    const float* b2  = (const float*)d_in[19];
    const float* l2g = (const float*)d_in[20];
    const float* l2b = (const float*)d_in[21];
    float* out = (float*)d_out;

    float *px, *pq, *pk, *pv, *pattn, *ptmp, *ph, *pKf, *pVf, *pS;
    cudaGetSymbolAddress((void**)&px,    g_x);
    cudaGetSymbolAddress((void**)&pq,    g_q);
    cudaGetSymbolAddress((void**)&pk,    g_k);
    cudaGetSymbolAddress((void**)&pv,    g_v);
    cudaGetSymbolAddress((void**)&pattn, g_attn);
    cudaGetSymbolAddress((void**)&ptmp,  g_tmp);
    cudaGetSymbolAddress((void**)&ph,    g_h);
    cudaGetSymbolAddress((void**)&pKf,   g_Kf);
    cudaGetSymbolAddress((void**)&pVf,   g_Vf);
    cudaGetSymbolAddress((void**)&pS,    g_S);

    copy_k<<<(T_*D_ + 255)/256, 256>>>(px, x, T_*D_);

    for (int l = 0; l < L_; l++) {
        const float* WqL = Wq + (long)l*D_*D_;
        const float* WkL = Wk + (long)l*D_*D_;
        const float* WvL = Wv + (long)l*D_*D_;
        const float* WoL = Wo + (long)l*D_*D_;
        const float* W1L = W1 + (long)l*D_*FFN_;
        const float* W2L = W2 + (long)l*FFN_*D_;
        const float* bqL = bq + (long)l*D_;
        const float* bkL = bk + (long)l*D_;
        const float* bvL = bv + (long)l*D_;
        const float* boL = bo + (long)l*D_;
        const float* b1L = b1 + (long)l*FFN_;
        const float* b2L = b2 + (long)l*D_;
        const float* PTl = pagetable + (long)l * NUM_PAGES * 2 * PAGE_ * H_ * DHD;

        dim3 gD(D_/128, T_/128, 1);   // 4096x1024 GEMMs
        // QKV projections
        gemm_k<false,false><<<gD, 256>>>(px, WqL, bqL, pq, T_, D_, D_, D_, D_, D_,
                                         1, 0, 0, 0, 0, 0, 0, 1.f);
        gemm_k<false,false><<<gD, 256>>>(px, WkL, bkL, pk, T_, D_, D_, D_, D_, D_,
                                         1, 0, 0, 0, 0, 0, 0, 1.f);
        gemm_k<false,false><<<gD, 256>>>(px, WvL, bvL, pv, T_, D_, D_, D_, D_, D_,
                                         1, 0, 0, 0, 0, 0, 0, 1.f);

        // dense KV gather (paged cache + new tokens)
        gather_kv_k<<<(B_*KV*D_)/256, 256>>>(PTl, kvidx, pk, pv);

        // scores: S[b,h] = 0.125 * Q[b,:,h,:] @ K[b,:,h,:]^T   (NT, batched)
        dim3 gS(KV/128, SQ/128, B_*H_);
        gemm_k<true,false><<<gS, 256>>>(pq, pKf, nullptr, pS,
            SQ, KV, DHD, D_, D_, KV,
            H_, (long)SQ*D_, 64L, (long)KV*D_, 64L,
            (long)H_*SQ*KV, (long)SQ*KV, 0.125f);

        softmax_k<<<B_*H_*SQ, 128>>>(pS);

        // PV: O[b,:,h,:] = P[b,h] @ V[b,:,h,:]   (NN, N=64 predicated)
        dim3 gP(1, SQ/128, B_*H_);
        gemm_k<false,false><<<gP, 256>>>(pS, pVf, nullptr, pattn,
            SQ, DHD, KV, KV, D_, D_,
            H_, (long)H_*SQ*KV, (long)SQ*KV, (long)KV*D_, 64L,
            (long)SQ*D_, 64L, 1.f);

        // output projection + residual + LN1
        gemm_k<false,false><<<gD, 256>>>(pattn, WoL, boL, ptmp, T_, D_, D_, D_, D_, D_,
                                         1, 0, 0, 0, 0, 0, 0, 1.f);
        add_ln_k<<<T_, 256>>>(px, ptmp, l1g + (long)l*D_, l1b + (long)l*D_);

        // FFN
        dim3 gF1(FFN_/128, T_/128, 1);
        gemm_k<false,true ><<<gF1, 256>>>(px, W1L, b1L, ph, T_, FFN_, D_, D_, FFN_, FFN_,
                                          1, 0, 0, 0, 0, 0, 0, 1.f);
        dim3 gF2(D_/128, T_/128, 1);
        gemm_k<false,false><<<gF2, 256>>>(ph, W2L, b2L, ptmp, T_, D_, FFN_, FFN_, D_, D_,
                                          1, 0, 0, 0, 0, 0, 0, 1.f);
        add_ln_k<<<T_, 256>>>(px, ptmp, l2g + (long)l*D_, l2b + (long)l*D_);
    }

    copy_k<<<(T_*D_ + 255)/256, 256>>>(out, px, T_*D_);
}